// round 4
// baseline (speedup 1.0000x reference)
#include <cuda_runtime.h>
#include <cuda_fp16.h>
#include <cstdint>

#define V_   45
#define H_   1500
#define H2_  3000
#define G4_  6000   // 4*H
#define SW_  50
#define SD_  10
#define HP_  1536   // H padded
#define H2P_ 3072
#define NSMALL_ 98  // 3 ctrl + 50 si + 45 dec
#define RESP_ 32    // resident row-PAIRS per block
#define TPB_ 512

// ---------------- persistent device scratch ----------------
__device__ float g_EV[2 * V_ * G4_];                  // [dir][v][row]
__device__ float g_WSTT[2 * G4_ * SW_];               // [(d*6000 + gr)*50 + k]
__device__ __align__(16) __half g_Whh[2 * G4_ * HP_];
__device__ __align__(16) __half g_Wsm[NSMALL_ * H2P_];
__device__ __align__(16) float g_gate[2 * G4_];
__device__ __align__(16) float g_h[H2P_];
__device__ float g_c[H2_];
__device__ float g_stack[2][SD_ * SW_];
__device__ float g_ctrl_raw[3];
__device__ float g_si_raw[SW_];
__device__ volatile unsigned g_arr[512];

// ---------------- flat distributed-flag grid barrier ----------------
__device__ __forceinline__ void gsync(unsigned gen, int nb) {
    __syncthreads();
    if (threadIdx.x == 0) { __threadfence(); g_arr[blockIdx.x] = gen; }
    if (threadIdx.x < nb) { while (g_arr[threadIdx.x] < gen) { } }
    __syncthreads();
    __threadfence();
    __syncthreads();
}

// ---------------- prep kernels ----------------
__global__ void prep_state(const float* __restrict__ h0, const float* __restrict__ c0,
                           const float* __restrict__ st0) {
    int i = blockIdx.x * blockDim.x + threadIdx.x;
    if (i < H2P_) {
        int d = i >= HP_;
        int j = i - d * HP_;
        g_h[i] = (j < H_) ? h0[d * H_ + j] : 0.f;
    }
    if (i < H2_) g_c[i] = c0[i];
    if (i < SD_ * SW_) g_stack[0][i] = st0[i];
    if (i < 512) g_arr[i] = 0u;
}

__global__ void conv_whh(const float* __restrict__ Wf, const float* __restrict__ Wb) {
    int idx = blockIdx.x * blockDim.x + threadIdx.x;
    if (idx >= 2 * G4_ * HP_) return;
    int d = idx / (G4_ * HP_);
    int rem = idx - d * (G4_ * HP_);
    int r = rem / HP_;
    int k = rem - r * HP_;
    const float* W = d ? Wb : Wf;
    float v = (k < H_) ? W[(size_t)r * H_ + k] : 0.f;
    g_Whh[idx] = __float2half(v);
}

__global__ void conv_small(const float* __restrict__ Wc, const float* __restrict__ Ws,
                           const float* __restrict__ Wd) {
    int idx = blockIdx.x * blockDim.x + threadIdx.x;
    if (idx >= NSMALL_ * H2P_) return;
    int row = idx / H2P_;
    int j = idx - row * H2P_;
    int d = j >= HP_;
    int jj = j - d * HP_;
    float v = 0.f;
    if (jj < H_) {
        int c = d * H_ + jj;
        const float* src; int r;
        if (row < 3)       { src = Wc; r = row; }
        else if (row < 53) { src = Ws; r = row - 3; }
        else               { src = Wd; r = row - 53; }
        v = src[(size_t)r * H2_ + c];
    }
    g_Wsm[idx] = __float2half(v);
}

__global__ void pack_wstt(const float* __restrict__ Wih_f, const float* __restrict__ Wih_b) {
    int idx = blockIdx.x * blockDim.x + threadIdx.x;
    if (idx >= 2 * G4_ * SW_) return;
    int gr2 = idx / SW_;
    int k = idx - gr2 * SW_;
    int d = gr2 / G4_;
    int r = gr2 - d * G4_;
    const float* W = d ? Wih_b : Wih_f;
    g_WSTT[idx] = W[(size_t)r * (H_ + SW_) + H_ + k];
}

__global__ void __launch_bounds__(256) prep_ev(
    const float* __restrict__ Wih_f, const float* __restrict__ Wih_b,
    const float* __restrict__ bih_f, const float* __restrict__ bhh_f,
    const float* __restrict__ bih_b, const float* __restrict__ bhh_b,
    const float* __restrict__ emb) {
    __shared__ float As[64][17];
    __shared__ float Bs[16][49];
    const int dir = blockIdx.y;
    const float* Wih = dir ? Wih_b : Wih_f;
    const float* bih = dir ? bih_b : bih_f;
    const float* bhh = dir ? bhh_b : bhh_f;
    const int r0 = blockIdx.x * 64;
    const int tid = threadIdx.x;
    const int ty = tid >> 4;
    const int tx = tid & 15;
    float acc[4][3] = {};
    for (int k0 = 0; k0 < H_; k0 += 16) {
        #pragma unroll
        for (int j = 0; j < 4; ++j) {
            int li = tid + j * 256;
            int row = li >> 4, kk = li & 15;
            int gr = r0 + row, gk = k0 + kk;
            As[row][kk] = (gr < G4_ && gk < H_) ? Wih[(size_t)gr * (H_ + SW_) + gk] : 0.f;
        }
        #pragma unroll
        for (int j = 0; j < 3; ++j) {
            int li = tid + j * 256;
            int v = li >> 4, kk = li & 15;
            int gk = k0 + kk;
            Bs[kk][v] = (v < V_ && gk < H_) ? emb[(size_t)v * H_ + gk] : 0.f;
        }
        __syncthreads();
        #pragma unroll
        for (int kk = 0; kk < 16; ++kk) {
            float a0 = As[ty * 4 + 0][kk], a1 = As[ty * 4 + 1][kk];
            float a2 = As[ty * 4 + 2][kk], a3 = As[ty * 4 + 3][kk];
            float b0 = Bs[kk][tx * 3 + 0], b1 = Bs[kk][tx * 3 + 1], b2 = Bs[kk][tx * 3 + 2];
            acc[0][0] = fmaf(a0, b0, acc[0][0]); acc[0][1] = fmaf(a0, b1, acc[0][1]); acc[0][2] = fmaf(a0, b2, acc[0][2]);
            acc[1][0] = fmaf(a1, b0, acc[1][0]); acc[1][1] = fmaf(a1, b1, acc[1][1]); acc[1][2] = fmaf(a1, b2, acc[1][2]);
            acc[2][0] = fmaf(a2, b0, acc[2][0]); acc[2][1] = fmaf(a2, b1, acc[2][1]); acc[2][2] = fmaf(a2, b2, acc[2][2]);
            acc[3][0] = fmaf(a3, b0, acc[3][0]); acc[3][1] = fmaf(a3, b1, acc[3][1]); acc[3][2] = fmaf(a3, b2, acc[3][2]);
        }
        __syncthreads();
    }
    #pragma unroll
    for (int i = 0; i < 4; ++i) {
        int r = r0 + ty * 4 + i;
        if (r >= G4_) continue;
        float bb = bih[r] + bhh[r];
        #pragma unroll
        for (int j = 0; j < 3; ++j) {
            int v = tx * 3 + j;
            if (v < V_) g_EV[((size_t)(dir * V_ + v)) * G4_ + r] = acc[i][j] + bb;
        }
    }
}

__device__ __forceinline__ void fma8(float& acc, uint4 u, float4 hA, float4 hB) {
    float2 f0 = __half22float2(*reinterpret_cast<__half2*>(&u.x));
    float2 f1 = __half22float2(*reinterpret_cast<__half2*>(&u.y));
    float2 f2 = __half22float2(*reinterpret_cast<__half2*>(&u.z));
    float2 f3 = __half22float2(*reinterpret_cast<__half2*>(&u.w));
    acc = fmaf(f0.x, hA.x, acc); acc = fmaf(f0.y, hA.y, acc);
    acc = fmaf(f1.x, hA.z, acc); acc = fmaf(f1.y, hA.w, acc);
    acc = fmaf(f2.x, hB.x, acc); acc = fmaf(f2.y, hB.y, acc);
    acc = fmaf(f3.x, hB.z, acc); acc = fmaf(f3.y, hB.w, acc);
}

// ---------------- persistent main kernel ----------------
__global__ void __launch_bounds__(TPB_, 1) rnn_main(
    const int* __restrict__ tokens,
    const float* __restrict__ bctrl, const float* __restrict__ bsi,
    const float* __restrict__ bdec,
    const float* __restrict__ WSTT,
    float* __restrict__ out, int T) {
    extern __shared__ __align__(16) char smem_raw[];
    __half* sW     = (__half*)smem_raw;                              // RESP_*2*HP_ halves
    float*  sh_h   = (float*)(smem_raw + (size_t)RESP_ * 2 * HP_ * 2);
    float*  s_stop = sh_h + H2P_;
    float*  s_si   = s_stop + SW_;

    const int bid  = blockIdx.x;
    const int tid  = threadIdx.x;
    const int lane = tid & 31;
    const int warp = tid >> 5;
    const int NB   = gridDim.x;
    const int DPB  = NB >> 1;
    const int dir  = (bid < DPB) ? 0 : ((bid < 2 * DPB) ? 1 : -1);
    const int bb   = (dir == 1) ? bid - DPB : bid;

    int pb = 0, p0 = 0;
    if (dir >= 0) {
        const int base = 3000 / DPB, rem = 3000 % DPB;
        pb = base + (bb < rem ? 1 : 0);
        p0 = bb * base + (bb < rem ? bb : rem);
    }
    const int resp = (pb < RESP_) ? pb : RESP_;
    const int spn  = pb - resp;
    const bool has_small = (bid < NSMALL_);

    // role of this warp in phase A
    int first = -1, stride = 0, plim = 0;
    bool is_res = false;
    if (dir >= 0) {
        if (warp < 12) { is_res = true; first = warp; stride = 12; plim = resp; }
        else {
            const int swn = has_small ? 3 : 4;
            const int sw = warp - 12;
            if (sw < swn) { first = sw; stride = swn; plim = spn; }
        }
    }

    // load resident weight pairs into SMEM (rows [2*p0, 2*p0+2*resp) of dir)
    if (dir >= 0) {
        const uint4* src = (const uint4*)(g_Whh + ((size_t)dir * G4_ + 2 * (size_t)p0) * HP_);
        const int n4 = resp * 2 * HP_ / 8;
        for (int i = tid; i < n4; i += TPB_) ((uint4*)sW)[i] = src[i];
    }

    unsigned gen = 1;

    for (int t = 0; t <= T; ++t) {
        // ---- stage h ----
        __syncthreads();
        for (int i = tid; i < H2P_ / 4; i += TPB_)
            ((float4*)sh_h)[i] = __ldcg((const float4*)g_h + i);
        __syncthreads();

        const int tok = (t < T) ? tokens[t] : 0;

        // ---- phase A: gate rows ----
        if (first >= 0 && t < T) {
            float acc[3][2] = {{0.f, 0.f}, {0.f, 0.f}, {0.f, 0.f}};
            #pragma unroll
            for (int c = 0; c < 2; ++c) {
                // h chunk slice in registers: floats [c*768, c*768+768) of dir half
                float4 hreg[6];
                const float4* sh4 = (const float4*)sh_h + dir * (HP_ / 4) + c * 192;
                #pragma unroll
                for (int it = 0; it < 3; ++it) {
                    const int o = lane + it * 32;
                    hreg[2 * it]     = sh4[2 * o];
                    hreg[2 * it + 1] = sh4[2 * o + 1];
                }
                #pragma unroll
                for (int ti = 0; ti < 3; ++ti) {
                    const int p = first + ti * stride;
                    if (p < plim) {
                        const uint4* W0;
                        if (is_res)
                            W0 = (const uint4*)(sW + (size_t)(2 * p) * HP_) + c * 96;
                        else
                            W0 = (const uint4*)(g_Whh + ((size_t)dir * G4_ + 2 * (size_t)(p0 + resp + p)) * HP_) + c * 96;
                        const uint4* W1 = W0 + (HP_ / 8);
                        #pragma unroll
                        for (int it = 0; it < 3; ++it) {
                            const int o = lane + it * 32;
                            uint4 u0 = W0[o];
                            uint4 u1 = W1[o];
                            fma8(acc[ti][0], u0, hreg[2 * it], hreg[2 * it + 1]);
                            fma8(acc[ti][1], u1, hreg[2 * it], hreg[2 * it + 1]);
                        }
                    }
                }
            }
            // reduce + store
            #pragma unroll
            for (int ti = 0; ti < 3; ++ti) {
                const int p = first + ti * stride;
                if (p < plim) {
                    float a0 = acc[ti][0], a1 = acc[ti][1];
                    #pragma unroll
                    for (int o = 16; o; o >>= 1) {
                        a0 += __shfl_xor_sync(0xffffffffu, a0, o);
                        a1 += __shfl_xor_sync(0xffffffffu, a1, o);
                    }
                    if (lane == 0) {
                        const int rglob = 2 * (p0 + (is_res ? p : resp + p));
                        const float2 ev = __ldcg((const float2*)&g_EV[((size_t)(dir * V_ + tok)) * G4_ + rglob]);
                        float2 r2; r2.x = a0 + ev.x; r2.y = a1 + ev.y;
                        *(float2*)&g_gate[dir * G4_ + rglob] = r2;
                    }
                }
            }
        }

        // ---- small rows (ctrl/si/dec): warp 15 of blocks 0..97 ----
        if (warp == 15 && has_small) {
            const int sid = bid;
            float bias; float* dst; bool doit;
            if (sid < 3)       { doit = (t < T); bias = bctrl[sid]; dst = &g_ctrl_raw[sid]; }
            else if (sid < 53) { doit = (t < T); bias = bsi[sid - 3]; dst = &g_si_raw[sid - 3]; }
            else               { doit = (t >= 1); bias = bdec[sid - 53]; dst = out + (size_t)(t - 1) * V_ + (sid - 53); }
            if (doit) {
                const uint4* W = (const uint4*)(g_Wsm + (size_t)sid * H2P_);
                const float4* s4 = (const float4*)sh_h;
                float acc = 0.f;
                #pragma unroll
                for (int it = 0; it < 12; ++it) {
                    const int o = lane + it * 32;
                    uint4 u = W[o];
                    fma8(acc, u, s4[2 * o], s4[2 * o + 1]);
                }
                #pragma unroll
                for (int o = 16; o; o >>= 1) acc += __shfl_xor_sync(0xffffffffu, acc, o);
                if (lane == 0) *dst = acc + bias;
            }
        }

        gsync(gen++, NB);
        if (t >= T) break;

        // ---- phase B ----
        const float* stOld = g_stack[t & 1];
        float* stNew = g_stack[(t + 1) & 1];

        if (tid < SW_) {
            const float c0r = __ldcg(&g_ctrl_raw[0]);
            const float c1r = __ldcg(&g_ctrl_raw[1]);
            const float c2r = __ldcg(&g_ctrl_raw[2]);
            const float m = fmaxf(c0r, fmaxf(c1r, c2r));
            const float e0 = __expf(c0r - m), e1 = __expf(c1r - m), e2 = __expf(c2r - m);
            const float inv = 1.f / (e0 + e1 + e2);
            float sv = tanhf(__ldcg(&g_si_raw[tid]));
            s_si[tid] = sv;
            s_stop[tid] = (e2 * inv) * __ldcg(&stOld[tid]) + (e0 * inv) * sv
                        + (e1 * inv) * __ldcg(&stOld[SW_ + tid]);
        }
        __syncthreads();

        const int gwarp = bid * 16 + warp;
        if (gwarp < H2_ / 2) {
            const int sub = lane >> 4;
            const int u = 2 * gwarp + sub;
            const int d = (u >= H_);
            const int i = u - d * H_;
            const int g = (lane >> 2) & 3;
            const int j = lane & 3;
            const float* wrow = WSTT + ((size_t)(d * G4_ + g * H_ + i)) * SW_;
            float sp = 0.f;
            #pragma unroll
            for (int k = j; k < SW_; k += 4) sp = fmaf(wrow[k], s_stop[k], sp);
            sp += __shfl_xor_sync(0xffffffffu, sp, 1);
            sp += __shfl_xor_sync(0xffffffffu, sp, 2);
            float gv = 0.f;
            if (j == 0) gv = __ldcg(&g_gate[d * G4_ + g * H_ + i]) + sp;
            float act = (g == 2) ? tanhf(gv) : (1.f / (1.f + __expf(-gv)));
            const int base = sub << 4;
            const float is = __shfl_sync(0xffffffffu, act, base + 0);
            const float fs = __shfl_sync(0xffffffffu, act, base + 4);
            const float gt = __shfl_sync(0xffffffffu, act, base + 8);
            const float os = __shfl_sync(0xffffffffu, act, base + 12);
            if (lane == base) {
                const float cc = fs * g_c[u] + is * gt;
                g_c[u] = cc;
                g_h[d * HP_ + i] = os * tanhf(cc);
            }
        }

        if (bid == 0 && tid < SD_ * SW_) {
            const float c0r = __ldcg(&g_ctrl_raw[0]);
            const float c1r = __ldcg(&g_ctrl_raw[1]);
            const float c2r = __ldcg(&g_ctrl_raw[2]);
            const float m = fmaxf(c0r, fmaxf(c1r, c2r));
            const float e0 = __expf(c0r - m), e1 = __expf(c1r - m), e2 = __expf(c2r - m);
            const float inv = 1.f / (e0 + e1 + e2);
            const float c0 = e0 * inv, c1 = e1 * inv, c2 = e2 * inv;
            const int dd = tid / SW_, k = tid - dd * SW_;
            const float up = (dd == 0) ? s_si[k] : __ldcg(&stOld[(dd - 1) * SW_ + k]);
            const float dn = (dd < SD_ - 1) ? __ldcg(&stOld[(dd + 1) * SW_ + k]) : 0.f;
            stNew[dd * SW_ + k] = c2 * __ldcg(&stOld[dd * SW_ + k]) + c0 * up + c1 * dn;
        }

        gsync(gen++, NB);
    }
}

// ---------------- launch ----------------
extern "C" void kernel_launch(void* const* d_in, const int* in_sizes, int n_in,
                              void* d_out, int out_size) {
    const int*   tokens  = (const int*)  d_in[0];
    const float* hidden0 = (const float*)d_in[1];
    const float* cell0   = (const float*)d_in[2];
    const float* stack0  = (const float*)d_in[3];
    const float* emb     = (const float*)d_in[4];
    const float* Wctrl   = (const float*)d_in[5];
    const float* bctrl   = (const float*)d_in[6];
    const float* Wsi     = (const float*)d_in[7];
    const float* bsi     = (const float*)d_in[8];
    const float* Wih_f   = (const float*)d_in[9];
    const float* Whh_f   = (const float*)d_in[10];
    const float* bih_f   = (const float*)d_in[11];
    const float* bhh_f   = (const float*)d_in[12];
    const float* Wih_b   = (const float*)d_in[13];
    const float* Whh_b   = (const float*)d_in[14];
    const float* bih_b   = (const float*)d_in[15];
    const float* bhh_b   = (const float*)d_in[16];
    const float* Wdec    = (const float*)d_in[17];
    const float* bdec    = (const float*)d_in[18];
    float* out = (float*)d_out;
    const int T = in_sizes[0];

    int dev = 0;
    cudaGetDevice(&dev);
    int nsm = 0;
    cudaDeviceGetAttribute(&nsm, cudaDevAttrMultiProcessorCount, dev);
    if (nsm <= 0) nsm = 148;

    const int SMEM = RESP_ * 2 * HP_ * 2 + H2P_ * 4 + 2 * SW_ * 4 + 256;
    cudaFuncSetAttribute(rnn_main, cudaFuncAttributeMaxDynamicSharedMemorySize, SMEM);

    float* wstt_ptr = nullptr;
    cudaGetSymbolAddress((void**)&wstt_ptr, g_WSTT);

    prep_state<<<(H2P_ + 255) / 256, 256>>>(hidden0, cell0, stack0);
    conv_whh<<<(2 * G4_ * HP_ + 255) / 256, 256>>>(Whh_f, Whh_b);
    conv_small<<<(NSMALL_ * H2P_ + 255) / 256, 256>>>(Wctrl, Wsi, Wdec);
    pack_wstt<<<(2 * G4_ * SW_ + 255) / 256, 256>>>(Wih_f, Wih_b);
    dim3 gev((G4_ + 63) / 64, 2);
    prep_ev<<<gev, 256>>>(Wih_f, Wih_b, bih_f, bhh_f, bih_b, bhh_b, emb);
    rnn_main<<<nsm, TPB_, SMEM>>>(tokens, bctrl, bsi, bdec, wstt_ptr, out, T);
}

// round 5
// speedup vs baseline: 1.5976x; 1.5976x over previous
#include <cuda_runtime.h>
#include <cuda_fp16.h>
#include <cstdint>

#define V_   45
#define H_   1500
#define H2_  3000
#define G4_  6000   // 4*H
#define SW_  50
#define SD_  10
#define HP_  1536   // H padded
#define H2P_ 3072
#define NSMALL_ 98  // 3 ctrl + 50 si + 45 dec
#define TPB_ 512

// ---------------- persistent device scratch ----------------
__device__ float g_EV[2 * V_ * G4_];                  // [dir][v][row] = Wih[:, :H]@emb[v] + bih + bhh
__device__ float g_WSTT[2 * G4_ * SW_];               // [(d*6000 + grow)*50 + k]
__device__ __align__(16) __half g_Whh[2 * G4_ * HP_];
__device__ __align__(16) __half g_Wsm[NSMALL_ * H2P_];
__device__ __align__(16) float g_h[H2P_];
__device__ float g_stack[2][SD_ * SW_];
__device__ float g_ctrl_raw[3];
__device__ float g_si_raw[SW_];
__device__ volatile unsigned g_arr[256];
__device__ volatile unsigned g_gen;
__device__ unsigned g_cs_cnt;
__device__ volatile unsigned g_cs_flag;

// ---------------- grid barrier: 2-hop, nanosleep backoff ----------------
__device__ __forceinline__ void gsync(unsigned gen, int nb) {
    __syncthreads();
    if (threadIdx.x == 0) { __threadfence(); g_arr[blockIdx.x] = gen; }
    if (blockIdx.x == 0) {
        if (threadIdx.x < nb) {
            while (g_arr[threadIdx.x] < gen) { __nanosleep(32); }
        }
        __syncthreads();
        if (threadIdx.x == 0) g_gen = gen;
    } else {
        if (threadIdx.x == 0) {
            while (g_gen < gen) { __nanosleep(32); }
        }
        __syncthreads();
    }
    __syncthreads();
}

// ---------------- fused misc prep ----------------
#define WSTT_N (2 * G4_ * SW_)          // 600000
#define WSM_N  (NSMALL_ * H2P_)         // 301056
__global__ void prep_misc(const float* __restrict__ h0, const float* __restrict__ st0,
                          const float* __restrict__ Wih_f, const float* __restrict__ Wih_b,
                          const float* __restrict__ Wc, const float* __restrict__ Ws,
                          const float* __restrict__ Wd) {
    int idx = blockIdx.x * blockDim.x + threadIdx.x;
    if (idx < WSTT_N) {
        int gr2 = idx / SW_;
        int k = idx - gr2 * SW_;
        int d = gr2 / G4_;
        int r = gr2 - d * G4_;
        const float* W = d ? Wih_b : Wih_f;
        g_WSTT[idx] = W[(size_t)r * (H_ + SW_) + H_ + k];
        return;
    }
    int j = idx - WSTT_N;
    if (j < WSM_N) {
        int row = j / H2P_;
        int jj = j - row * H2P_;
        int d = jj >= HP_;
        int c = jj - d * HP_;
        float v = 0.f;
        if (c < H_) {
            int col = d * H_ + c;
            const float* src; int r;
            if (row < 3)       { src = Wc; r = row; }
            else if (row < 53) { src = Ws; r = row - 3; }
            else               { src = Wd; r = row - 53; }
            v = src[(size_t)r * H2_ + col];
        }
        g_Wsm[j] = __float2half(v);
        return;
    }
    int m = j - WSM_N;
    if (m < H2P_) {
        int d = m >= HP_;
        int i = m - d * HP_;
        g_h[m] = (i < H_) ? h0[d * H_ + i] : 0.f;
    } else if (m < H2P_ + SD_ * SW_) {
        g_stack[0][m - H2P_] = st0[m - H2P_];
    } else if (m < H2P_ + SD_ * SW_ + 256) {
        g_arr[m - H2P_ - SD_ * SW_] = 0u;
    } else if (m == H2P_ + SD_ * SW_ + 256) {
        g_cs_cnt = 0u; g_cs_flag = 0u; g_gen = 0u;
    }
}
#define MISC_N (WSTT_N + WSM_N + H2P_ + SD_ * SW_ + 257)

__global__ void conv_whh(const float* __restrict__ Wf, const float* __restrict__ Wb) {
    int idx = blockIdx.x * blockDim.x + threadIdx.x;
    if (idx >= 2 * G4_ * HP_) return;
    int d = idx / (G4_ * HP_);
    int rem = idx - d * (G4_ * HP_);
    int r = rem / HP_;
    int k = rem - r * HP_;
    const float* W = d ? Wb : Wf;
    float v = (k < H_) ? W[(size_t)r * H_ + k] : 0.f;
    g_Whh[idx] = __float2half(v);
}

__global__ void __launch_bounds__(256) prep_ev(
    const float* __restrict__ Wih_f, const float* __restrict__ Wih_b,
    const float* __restrict__ bih_f, const float* __restrict__ bhh_f,
    const float* __restrict__ bih_b, const float* __restrict__ bhh_b,
    const float* __restrict__ emb) {
    __shared__ float As[64][17];
    __shared__ float Bs[16][49];
    const int dir = blockIdx.y;
    const float* Wih = dir ? Wih_b : Wih_f;
    const float* bih = dir ? bih_b : bih_f;
    const float* bhh = dir ? bhh_b : bhh_f;
    const int r0 = blockIdx.x * 64;
    const int tid = threadIdx.x;
    const int ty = tid >> 4;
    const int tx = tid & 15;
    float acc[4][3] = {};
    for (int k0 = 0; k0 < H_; k0 += 16) {
        #pragma unroll
        for (int j = 0; j < 4; ++j) {
            int li = tid + j * 256;
            int row = li >> 4, kk = li & 15;
            int gr = r0 + row, gk = k0 + kk;
            As[row][kk] = (gr < G4_ && gk < H_) ? Wih[(size_t)gr * (H_ + SW_) + gk] : 0.f;
        }
        #pragma unroll
        for (int j = 0; j < 3; ++j) {
            int li = tid + j * 256;
            int v = li >> 4, kk = li & 15;
            int gk = k0 + kk;
            Bs[kk][v] = (v < V_ && gk < H_) ? emb[(size_t)v * H_ + gk] : 0.f;
        }
        __syncthreads();
        #pragma unroll
        for (int kk = 0; kk < 16; ++kk) {
            float a0 = As[ty * 4 + 0][kk], a1 = As[ty * 4 + 1][kk];
            float a2 = As[ty * 4 + 2][kk], a3 = As[ty * 4 + 3][kk];
            float b0 = Bs[kk][tx * 3 + 0], b1 = Bs[kk][tx * 3 + 1], b2 = Bs[kk][tx * 3 + 2];
            acc[0][0] = fmaf(a0, b0, acc[0][0]); acc[0][1] = fmaf(a0, b1, acc[0][1]); acc[0][2] = fmaf(a0, b2, acc[0][2]);
            acc[1][0] = fmaf(a1, b0, acc[1][0]); acc[1][1] = fmaf(a1, b1, acc[1][1]); acc[1][2] = fmaf(a1, b2, acc[1][2]);
            acc[2][0] = fmaf(a2, b0, acc[2][0]); acc[2][1] = fmaf(a2, b1, acc[2][1]); acc[2][2] = fmaf(a2, b2, acc[2][2]);
            acc[3][0] = fmaf(a3, b0, acc[3][0]); acc[3][1] = fmaf(a3, b1, acc[3][1]); acc[3][2] = fmaf(a3, b2, acc[3][2]);
        }
        __syncthreads();
    }
    #pragma unroll
    for (int i = 0; i < 4; ++i) {
        int r = r0 + ty * 4 + i;
        if (r >= G4_) continue;
        float bb = bih[r] + bhh[r];
        #pragma unroll
        for (int j = 0; j < 3; ++j) {
            int v = tx * 3 + j;
            if (v < V_) g_EV[((size_t)(dir * V_ + v)) * G4_ + r] = acc[i][j] + bb;
        }
    }
}

__device__ __forceinline__ void fma8(float& acc, uint4 u, float4 hA, float4 hB) {
    float2 f0 = __half22float2(*reinterpret_cast<__half2*>(&u.x));
    float2 f1 = __half22float2(*reinterpret_cast<__half2*>(&u.y));
    float2 f2 = __half22float2(*reinterpret_cast<__half2*>(&u.z));
    float2 f3 = __half22float2(*reinterpret_cast<__half2*>(&u.w));
    acc = fmaf(f0.x, hA.x, acc); acc = fmaf(f0.y, hA.y, acc);
    acc = fmaf(f1.x, hA.z, acc); acc = fmaf(f1.y, hA.w, acc);
    acc = fmaf(f2.x, hB.x, acc); acc = fmaf(f2.y, hB.y, acc);
    acc = fmaf(f3.x, hB.z, acc); acc = fmaf(f3.y, hB.w, acc);
}

// full-length (2H) small-row dot over sh_h
__device__ __forceinline__ float small_dot(int sid, const float* sh_h, int lane) {
    const uint4* W = (const uint4*)(g_Wsm + (size_t)sid * H2P_);
    const float4* s4 = (const float4*)sh_h;
    float acc = 0.f;
    #pragma unroll
    for (int it = 0; it < 12; ++it) {
        const int o = lane + it * 32;
        uint4 u = W[o];
        fma8(acc, u, s4[2 * o], s4[2 * o + 1]);
    }
    #pragma unroll
    for (int o = 16; o; o >>= 1) acc += __shfl_xor_sync(0xffffffffu, acc, o);
    return acc;
}

// ---------------- persistent main kernel: one grid barrier per step ----------------
__global__ void __launch_bounds__(TPB_, 1) rnn_main(
    const int* __restrict__ tokens, const float* __restrict__ cell0,
    const float* __restrict__ bctrl, const float* __restrict__ bsi,
    const float* __restrict__ bdec,
    float* __restrict__ out, int T) {
    __shared__ __align__(16) float sh_h[H2P_];
    __shared__ float s_gate[80];
    __shared__ float s_stop[SW_];

    const int bid  = blockIdx.x;
    const int tid  = threadIdx.x;
    const int lane = tid & 31;
    const int warp = tid >> 5;
    const int NB   = gridDim.x;

    // block-owned contiguous unit range
    const int ubase = H2_ / NB, urem = H2_ % NB;
    const int un = ubase + (bid < urem ? 1 : 0);
    const int u0 = bid * ubase + (bid < urem ? bid : urem);
    const int nrows = 4 * un;
    const bool has_small = (bid < NSMALL_);
    const int dstride = has_small ? 15 : 16;
    const bool is_smallw = (has_small && warp == 15);

    // persistent cell state in registers (lane0's copy authoritative)
    float creg0 = 0.f, creg1 = 0.f;
    int myu0 = -1, myu1 = -1;
    if (warp < un)      { myu0 = u0 + warp;      creg0 = cell0[myu0]; }
    if (warp + 16 < un) { myu1 = u0 + warp + 16; creg1 = cell0[myu1]; }

    unsigned gen = 0;

    for (int t = 0; t <= T; ++t) {
        // ---- stage h (written last step, fenced by barrier) ----
        __syncthreads();
        for (int i = tid; i < H2P_ / 4; i += TPB_)
            ((float4*)sh_h)[i] = __ldcg((const float4*)g_h + i);
        __syncthreads();

        if (t == T) {   // final logits row for step T-1
            if (is_smallw && bid >= 53) {
                float acc = small_dot(bid, sh_h, lane);
                if (lane == 0) out[(size_t)(T - 1) * V_ + (bid - 53)] = acc + bdec[bid - 53];
            }
            break;
        }
        const int tok = tokens[t];

        // ---- small rows first (ctrl/si publish with flag; dec straight to out) ----
        if (is_smallw) {
            const int sid = bid;
            if (sid < 53) {
                float acc = small_dot(sid, sh_h, lane);
                if (lane == 0) {
                    if (sid < 3) g_ctrl_raw[sid] = acc + bctrl[sid];
                    else         g_si_raw[sid - 3] = acc + bsi[sid - 3];
                    __threadfence();
                    unsigned r = atomicAdd(&g_cs_cnt, 1u);
                    if (r == 53u * (unsigned)(t + 1) - 1u) { __threadfence(); g_cs_flag = (unsigned)(t + 1); }
                }
            } else if (t >= 1) {
                float acc = small_dot(sid, sh_h, lane);
                if (lane == 0) out[(size_t)(t - 1) * V_ + (sid - 53)] = acc + bdec[sid - 53];
            }
        }

        // ---- big gate-row dots into block-local s_gate ----
        if (!is_smallw) {
            for (int rl = warp; rl < nrows; rl += 2 * dstride) {
                const int rl2 = rl + dstride;
                const bool v2 = (rl2 < nrows);
                // row 0
                const int ul0 = rl >> 2, g0 = rl & 3;
                const int uu0 = u0 + ul0;
                const int d0 = (uu0 >= H_);
                const int i0 = uu0 - d0 * H_;
                const int grow0 = g0 * H_ + i0;
                // row 1
                const int rlb = v2 ? rl2 : rl;
                const int ul1 = rlb >> 2, g1 = rlb & 3;
                const int uu1 = u0 + ul1;
                const int d1 = (uu1 >= H_);
                const int i1 = uu1 - d1 * H_;
                const int grow1 = g1 * H_ + i1;

                float ev0 = 0.f, ev1 = 0.f;
                if (lane == 0) {
                    ev0 = __ldg(&g_EV[((size_t)(d0 * V_ + tok)) * G4_ + grow0]);
                    ev1 = __ldg(&g_EV[((size_t)(d1 * V_ + tok)) * G4_ + grow1]);
                }
                const uint4* W0 = (const uint4*)(g_Whh + ((size_t)(d0 * G4_ + grow0)) * HP_);
                const uint4* W1 = (const uint4*)(g_Whh + ((size_t)(d1 * G4_ + grow1)) * HP_);
                const float4* hb0 = (const float4*)(sh_h + d0 * HP_);
                const float4* hb1 = (const float4*)(sh_h + d1 * HP_);
                float a0 = 0.f, a1 = 0.f;
                #pragma unroll
                for (int it = 0; it < 6; ++it) {
                    const int o = lane + it * 32;
                    uint4 w0 = W0[o];
                    uint4 w1 = W1[o];
                    fma8(a0, w0, hb0[2 * o], hb0[2 * o + 1]);
                    fma8(a1, w1, hb1[2 * o], hb1[2 * o + 1]);
                }
                #pragma unroll
                for (int o = 16; o; o >>= 1) {
                    a0 += __shfl_xor_sync(0xffffffffu, a0, o);
                    a1 += __shfl_xor_sync(0xffffffffu, a1, o);
                }
                if (lane == 0) {
                    s_gate[rl] = a0 + ev0;
                    if (v2) s_gate[rl2] = a1 + ev1;
                }
            }
        }

        // ---- wait for ctrl/si (one poller per block) ----
        if (tid == 0) {
            while (g_cs_flag < (unsigned)(t + 1)) { __nanosleep(16); }
        }
        __syncthreads();

        // ---- s_stop (+ stack update on block 0) ----
        const float* stOld = g_stack[t & 1];
        float* stNew = g_stack[(t + 1) & 1];
        if (tid < SW_ + 450) {
            const float c0r = __ldcg(&g_ctrl_raw[0]);
            const float c1r = __ldcg(&g_ctrl_raw[1]);
            const float c2r = __ldcg(&g_ctrl_raw[2]);
            const float m = fmaxf(c0r, fmaxf(c1r, c2r));
            const float e0 = __expf(c0r - m), e1 = __expf(c1r - m), e2 = __expf(c2r - m);
            const float inv = 1.f / (e0 + e1 + e2);
            const float c0 = e0 * inv, c1 = e1 * inv, c2 = e2 * inv;
            if (tid < SW_) {
                const float sv = tanhf(__ldcg(&g_si_raw[tid]));
                const float sp = c2 * __ldcg(&stOld[tid]) + c0 * sv + c1 * __ldcg(&stOld[SW_ + tid]);
                s_stop[tid] = sp;
                if (bid == 0) stNew[tid] = sp;         // stack row 0
            } else if (bid == 0) {
                const int idx = tid - SW_;              // 0..449 -> rows 1..9
                const int dd = 1 + idx / SW_;
                const int k = idx - (dd - 1) * SW_;
                const float up = __ldcg(&stOld[(dd - 1) * SW_ + k]);
                const float dn = (dd < SD_ - 1) ? __ldcg(&stOld[(dd + 1) * SW_ + k]) : 0.f;
                stNew[dd * SW_ + k] = c2 * __ldcg(&stOld[dd * SW_ + k]) + c0 * up + c1 * dn;
            }
        }
        __syncthreads();

        // ---- pointwise LSTM update (warp per owned unit) ----
        #pragma unroll
        for (int q = 0; q < 2; ++q) {
            const int u = q ? myu1 : myu0;
            if (u < 0) continue;
            const int ul = u - u0;
            const int d = (u >= H_);
            const int i = u - d * H_;
            const int g8 = lane >> 3;
            const int k0 = lane & 7;
            const float* wst = g_WSTT + ((size_t)(d * G4_ + g8 * H_ + i)) * SW_;
            float sp = 0.f;
            #pragma unroll
            for (int j = 0; j < 7; ++j) {
                const int k = k0 + 8 * j;
                if (k < SW_) sp = fmaf(wst[k], s_stop[k], sp);
            }
            sp += __shfl_xor_sync(0xffffffffu, sp, 1);
            sp += __shfl_xor_sync(0xffffffffu, sp, 2);
            sp += __shfl_xor_sync(0xffffffffu, sp, 4);
            const float tot = s_gate[4 * ul + g8] + sp;
            const float act = (g8 == 2) ? tanhf(tot) : (1.f / (1.f + __expf(-tot)));
            const float is = __shfl_sync(0xffffffffu, act, 0);
            const float fs = __shfl_sync(0xffffffffu, act, 8);
            const float gt = __shfl_sync(0xffffffffu, act, 16);
            const float os = __shfl_sync(0xffffffffu, act, 24);
            if (lane == 0) {
                float& cr = q ? creg1 : creg0;
                const float cc = fs * cr + is * gt;
                cr = cc;
                g_h[d * HP_ + i] = os * tanhf(cc);
            }
        }

        gsync(++gen, NB);
    }
}

// ---------------- launch ----------------
extern "C" void kernel_launch(void* const* d_in, const int* in_sizes, int n_in,
                              void* d_out, int out_size) {
    const int*   tokens  = (const int*)  d_in[0];
    const float* hidden0 = (const float*)d_in[1];
    const float* cell0   = (const float*)d_in[2];
    const float* stack0  = (const float*)d_in[3];
    const float* emb     = (const float*)d_in[4];
    const float* Wctrl   = (const float*)d_in[5];
    const float* bctrl   = (const float*)d_in[6];
    const float* Wsi     = (const float*)d_in[7];
    const float* bsi     = (const float*)d_in[8];
    const float* Wih_f   = (const float*)d_in[9];
    const float* Whh_f   = (const float*)d_in[10];
    const float* bih_f   = (const float*)d_in[11];
    const float* bhh_f   = (const float*)d_in[12];
    const float* Wih_b   = (const float*)d_in[13];
    const float* Whh_b   = (const float*)d_in[14];
    const float* bih_b   = (const float*)d_in[15];
    const float* bhh_b   = (const float*)d_in[16];
    const float* Wdec    = (const float*)d_in[17];
    const float* bdec    = (const float*)d_in[18];
    float* out = (float*)d_out;
    const int T = in_sizes[0];

    int dev = 0;
    cudaGetDevice(&dev);
    int nsm = 0;
    cudaDeviceGetAttribute(&nsm, cudaDevAttrMultiProcessorCount, dev);
    if (nsm <= 0) nsm = 148;
    if (nsm > 256) nsm = 256;

    prep_misc<<<(MISC_N + 255) / 256, 256>>>(hidden0, stack0, Wih_f, Wih_b, Wctrl, Wsi, Wdec);
    conv_whh<<<(2 * G4_ * HP_ + 255) / 256, 256>>>(Whh_f, Whh_b);
    dim3 gev((G4_ + 63) / 64, 2);
    prep_ev<<<gev, 256>>>(Wih_f, Wih_b, bih_f, bhh_f, bih_b, bhh_b, emb);
    rnn_main<<<nsm, TPB_>>>(tokens, cell0, bctrl, bsi, bdec, out, T);
}